// round 16
// baseline (speedup 1.0000x reference)
#include <cuda_runtime.h>

#define NND 20000
#define NE  640000
#define NG  256
#define HD  128
#define ED  64
#define GD  64
#define HID 128

#define PE  68
#define PX  132
#define PU  68
#define PA  36
#define PB  136
#define PB3 72

// ---------------- scratch ----------------
__device__ float d_gmap[NG * HID];
__device__ float d_nsum[NND];
__device__ float d_maggr[(size_t)NND * HID];
__device__ float d_gsumh[NG];
__device__ float d_gsume[NG];
__device__ float d_haggr[NG * HID];
__device__ float d_eaggr[NG * ED];

// ---------------- helpers ----------------
__device__ __forceinline__ void mma8(float* c, const unsigned* a, const unsigned* b) {
    asm volatile(
        "mma.sync.aligned.m16n8k8.row.col.f32.tf32.tf32.f32 "
        "{%0,%1,%2,%3}, {%4,%5,%6,%7}, {%8,%9}, {%0,%1,%2,%3};"
        : "+f"(c[0]), "+f"(c[1]), "+f"(c[2]), "+f"(c[3])
        : "r"(a[0]), "r"(a[1]), "r"(a[2]), "r"(a[3]), "r"(b[0]), "r"(b[1]));
}
__device__ __forceinline__ void cp16(void* s, const void* g) {
    unsigned sa = (unsigned)__cvta_generic_to_shared(s);
    asm volatile("cp.async.cg.shared.global [%0], [%1], 16;" :: "r"(sa), "l"(g));
}
#define CP_COMMIT asm volatile("cp.async.commit_group;")
#define CP_WAIT0  asm volatile("cp.async.wait_group 0;")
#define CP_WAIT1  asm volatile("cp.async.wait_group 1;")

__device__ __forceinline__ void red4(float* g, float4 v) {
    asm volatile("red.global.add.v4.f32 [%0], {%1,%2,%3,%4};"
                 :: "l"(g), "f"(v.x), "f"(v.y), "f"(v.z), "f"(v.w) : "memory");
}
__device__ __forceinline__ void ldsmA(unsigned* a, const float* p) {
    unsigned addr = (unsigned)__cvta_generic_to_shared(p);
    asm volatile("ldmatrix.sync.aligned.m8n8.x4.shared.b16 {%0,%1,%2,%3}, [%4];"
                 : "=r"(a[0]), "=r"(a[1]), "=r"(a[2]), "=r"(a[3]) : "r"(addr));
}

// warp-tile GEMM step over one 32-wide k-tile. mt=2 fixed, NT n-tiles of 8 cols.
template <int NT>
__device__ __forceinline__ void gemm_tile(float (*c)[NT][4],
                                          const float* __restrict__ At, int padA, int coff,
                                          const float* __restrict__ Bt, int padB,
                                          int rbase, int cbase, int g, int kq) {
    const int lane = (g << 2) | kq;
    const int rsel = lane & 15;
    const int csel = (lane >> 4) << 2;
#pragma unroll
    for (int k8 = 0; k8 < 4; k8++) {
        unsigned a[2][4];
#pragma unroll
        for (int mt = 0; mt < 2; mt++) {
            const float* p = At + (rbase + mt * 16 + rsel) * padA + coff + k8 * 8 + csel;
            ldsmA(a[mt], p);
        }
        unsigned b[NT][2];
#pragma unroll
        for (int nt = 0; nt < NT; nt++) {
            const float* p = Bt + (k8 * 8 + kq) * padB + cbase + nt * 8 + g;
            b[nt][0] = __float_as_uint(p[0]);
            b[nt][1] = __float_as_uint(p[4 * padB]);
        }
#pragma unroll
        for (int mt = 0; mt < 2; mt++)
#pragma unroll
            for (int nt = 0; nt < NT; nt++) mma8(c[mt][nt], a[mt], b[nt]);
    }
}

// ---------------- merged init + g_map (32768 threads) ----------------
__global__ void k_initg(const float* __restrict__ g, const float* __restrict__ Wmap,
                        const float* __restrict__ bmap) {
    int i = blockIdx.x * blockDim.x + threadIdx.x;   // 0..32767
    int r = i >> 7, c = i & 127;
    float s = bmap[c];
#pragma unroll 8
    for (int k = 0; k < GD; k++) s += __ldg(g + r * GD + k) * __ldg(Wmap + k * HID + c);
    d_gmap[i] = s;
    d_haggr[i] = 0.f;
    if (i < NG) { d_gsumh[i] = 0.f; d_gsume[i] = 0.f; }
    if (i < NG * ED) d_eaggr[i] = 0.f;
}

// ---------------- node->graph aggregation + zero-fill ----------------
__global__ void k_hagg(const float* __restrict__ h, const int* __restrict__ batch,
                       const float* __restrict__ Wha, const float* __restrict__ bhaP) {
    int w = (blockIdx.x * blockDim.x + threadIdx.x) >> 5;
    int lane = threadIdx.x & 31;
    if (w >= NND) return;
    *(float4*)(d_maggr + (size_t)w * HID + lane * 4) = make_float4(0.f, 0.f, 0.f, 0.f);
    if (lane == 0) d_nsum[w] = 0.f;
    float4 hv = *(const float4*)(h + (size_t)w * HD + lane * 4);
    float4 wv = *(const float4*)(Wha + lane * 4);
    float s = hv.x * wv.x + hv.y * wv.y + hv.z * wv.z + hv.w * wv.w;
#pragma unroll
    for (int off = 16; off; off >>= 1) s += __shfl_xor_sync(0xffffffffu, s, off);
    int b = batch[w];
    float ew = expf(s + bhaP[0]);
    if (lane == 0) atomicAdd(&d_gsumh[b], ew);
    red4(d_haggr + b * HD + lane * 4,
         make_float4(hv.x * ew, hv.y * ew, hv.z * ew, hv.w * ew));
}

// ---------------- fused edge kernel (exact R8 configuration) ----------------
__global__ __launch_bounds__(256, 1) void k_edge(
    const float* __restrict__ h, const float* __restrict__ e,
    const int* __restrict__ eidx, const int* __restrict__ batch,
    const float* __restrict__ Wm1, const float* __restrict__ bm1,
    const float* __restrict__ Wm2, const float* __restrict__ bm2,
    const float* __restrict__ Wma, const float* __restrict__ bmaP,
    const float* __restrict__ We1, const float* __restrict__ be1,
    const float* __restrict__ We2, const float* __restrict__ be2,
    const float* __restrict__ Wea, const float* __restrict__ beaP,
    float* __restrict__ eout)
{
    extern __shared__ float smp[];
    float* sE    = smp;                       // 128*PE
    float* sX    = sE + 128 * PE;             // 128*PX
    float* sA    = sX + 128 * PX;             // 3*128*PA
    float* sU    = sA;                        // alias: sA dead after GEMM1
    float* sB    = sA + 3 * 128 * PA;         // 3*32*PB
    float* sWma  = sB + 3 * 32 * PB;
    float* sWea  = sWma + 128;
    float* sMatt = sWea + 64;
    float* sWeat = sMatt + 128;
    float* sBm1  = sWeat + 128;
    float* sBm2  = sBm1 + 128;
    float* sBe1  = sBm2 + 128;
    float* sBe2  = sBe1 + 64;
    int* sDst = (int*)(sBe2 + 64);
    int* sSrc = sDst + 128;
    int* sBat = sSrc + 128;

    const int tid  = threadIdx.x;
    const int lane = tid & 31;
    const int wid  = tid >> 5;
    const int wy   = wid >> 1;
    const int wx   = wid & 1;
    const int g    = lane >> 2;
    const int kq   = lane & 3;
    const int e0   = blockIdx.x * 128;

    if (tid < 128) {
        int d = eidx[NE + e0 + tid];
        sDst[tid] = d;
        sSrc[tid] = eidx[e0 + tid];
        sBat[tid] = batch[d];
        sWma[tid] = Wma[tid];
        sMatt[tid] = bmaP[0];
        sBm1[tid] = bm1[tid];
        sBm2[tid] = bm2[tid];
    }
    if (tid < 64) { sWea[tid] = Wea[tid]; sBe1[tid] = be1[tid]; sBe2[tid] = be2[tid]; }
    __syncthreads();

#pragma unroll
    for (int i = 0; i < 8; i++) {
        int c = tid + i * 256;
        int row = c >> 4, q = c & 15;
        cp16(sE + row * PE + q * 4, e + (size_t)(e0 + row) * ED + q * 4);
    }
#pragma unroll
    for (int i = 0; i < 4; i++) {
        int c = tid + i * 256;
        int row = c >> 3, q = c & 7;
        cp16(sA + row * PA + q * 4, h + (size_t)sDst[row] * HD + q * 4);
    }
#pragma unroll
    for (int i = 0; i < 4; i++) {
        int c = tid + i * 256;
        int row = c >> 5, q = c & 31;
        cp16(sB + row * PB + q * 4, Wm1 + (size_t)row * HID + q * 4);
    }
    CP_COMMIT;
#pragma unroll
    for (int i = 0; i < 4; i++) {
        int c = tid + i * 256;
        int row = c >> 3, q = c & 7;
        cp16(sA + 128 * PA + row * PA + q * 4, h + (size_t)sDst[row] * HD + 32 + q * 4);
    }
#pragma unroll
    for (int i = 0; i < 4; i++) {
        int c = tid + i * 256;
        int row = c >> 5, q = c & 31;
        cp16(sB + 32 * PB + row * PB + q * 4, Wm1 + (size_t)(32 + row) * HID + q * 4);
    }
    CP_COMMIT;

    // ================= GEMM1: [128,320] @ Wm1 -> X (3-stage) =================
    float acc[2][8][4];
#pragma unroll
    for (int mt = 0; mt < 2; mt++)
#pragma unroll
        for (int nt = 0; nt < 8; nt++)
#pragma unroll
            for (int i = 0; i < 4; i++) acc[mt][nt][i] = 0.f;

    for (int t = 0; t < 10; t++) {
        if (t < 9) { CP_WAIT1; } else { CP_WAIT0; }
        __syncthreads();
        int tn = t + 2;
        if (tn <= 9) {
            int buf = tn - (tn / 3) * 3;
            if (tn < 8) {
#pragma unroll
                for (int i = 0; i < 4; i++) {
                    int c = tid + i * 256;
                    int row = c >> 3, q = c & 7;
                    const float* src = (tn < 4)
                        ? h + (size_t)sDst[row] * HD + tn * 32 + q * 4
                        : h + (size_t)sSrc[row] * HD + (tn - 4) * 32 + q * 4;
                    cp16(sA + buf * 128 * PA + row * PA + q * 4, src);
                }
            }
#pragma unroll
            for (int i = 0; i < 4; i++) {
                int c = tid + i * 256;
                int row = c >> 5, q = c & 31;
                cp16(sB + buf * 32 * PB + row * PB + q * 4,
                     Wm1 + (size_t)(tn * 32 + row) * HID + q * 4);
            }
            CP_COMMIT;
        }
        int cbuf = t - (t / 3) * 3;
        const float* At; int padA, coff;
        if (t < 8) { At = sA + cbuf * 128 * PA; padA = PA; coff = 0; }
        else       { At = sE; padA = PE; coff = (t - 8) * 32; }
        gemm_tile<8>(acc, At, padA, coff, sB + cbuf * 32 * PB, PB, wy * 32, wx * 64, g, kq);
    }

    // epilogue 1
#pragma unroll
    for (int mt = 0; mt < 2; mt++) {
        int r0 = wy * 32 + mt * 16 + g;
#pragma unroll
        for (int nt = 0; nt < 8; nt++) {
            int col = wx * 64 + nt * 8 + kq * 2;
            float b0 = sBm1[col], b1 = sBm1[col + 1];
            *(float2*)&sX[r0 * PX + col] =
                make_float2(fmaxf(acc[mt][nt][0] + b0, 0.f), fmaxf(acc[mt][nt][1] + b1, 0.f));
            *(float2*)&sX[(r0 + 8) * PX + col] =
                make_float2(fmaxf(acc[mt][nt][2] + b0, 0.f), fmaxf(acc[mt][nt][3] + b1, 0.f));
        }
    }
    __syncthreads();

#pragma unroll
    for (int i = 0; i < 4; i++) {
        int c = tid + i * 256;
        int row = c >> 5, q = c & 31;
        cp16(sB + row * PB + q * 4, Wm2 + (size_t)row * HID + q * 4);
    }
    CP_COMMIT;

    // ================= GEMM2 =================
#pragma unroll
    for (int mt = 0; mt < 2; mt++)
#pragma unroll
        for (int nt = 0; nt < 8; nt++)
#pragma unroll
            for (int i = 0; i < 4; i++) acc[mt][nt][i] = 0.f;

    for (int t = 0; t < 4; t++) {
        CP_WAIT0;
        __syncthreads();
        if (t < 3) {
            int tn = t + 1;
#pragma unroll
            for (int i = 0; i < 4; i++) {
                int c = tid + i * 256;
                int row = c >> 5, q = c & 31;
                cp16(sB + ((tn & 1) * 32 * PB) + row * PB + q * 4,
                     Wm2 + (size_t)(tn * 32 + row) * HID + q * 4);
            }
            CP_COMMIT;
        }
        gemm_tile<8>(acc, sX, PX, t * 32, sB + (t & 1) * 32 * PB, PB, wy * 32, wx * 64, g, kq);
    }
    __syncthreads();

    // epilogue 2
    {
        float pa[4] = {0.f, 0.f, 0.f, 0.f};
#pragma unroll
        for (int mt = 0; mt < 2; mt++) {
            int r0 = wy * 32 + mt * 16 + g;
#pragma unroll
            for (int nt = 0; nt < 8; nt++) {
                int col = wx * 64 + nt * 8 + kq * 2;
                float b0 = sBm2[col], b1 = sBm2[col + 1];
                float v0 = fmaxf(acc[mt][nt][0] + b0, 0.f);
                float v1 = fmaxf(acc[mt][nt][1] + b1, 0.f);
                float v2 = fmaxf(acc[mt][nt][2] + b0, 0.f);
                float v3 = fmaxf(acc[mt][nt][3] + b1, 0.f);
                *(float2*)&sX[r0 * PX + col]       = make_float2(v0, v1);
                *(float2*)&sX[(r0 + 8) * PX + col] = make_float2(v2, v3);
                float w0 = sWma[col], w1 = sWma[col + 1];
                pa[mt * 2 + 0] += v0 * w0 + v1 * w1;
                pa[mt * 2 + 1] += v2 * w0 + v3 * w1;
            }
        }
#pragma unroll
        for (int off = 1; off <= 2; off <<= 1)
#pragma unroll
            for (int i = 0; i < 4; i++) pa[i] += __shfl_xor_sync(0xffffffffu, pa[i], off);
        if (kq == 0) {
            atomicAdd(&sMatt[wy * 32 + g],      pa[0]);
            atomicAdd(&sMatt[wy * 32 + g + 8],  pa[1]);
            atomicAdd(&sMatt[wy * 32 + g + 16], pa[2]);
            atomicAdd(&sMatt[wy * 32 + g + 24], pa[3]);
        }
    }
    __syncthreads();

    if (tid < 128) {
        float w = expf(sMatt[tid]);
        sMatt[tid] = w;
        atomicAdd(&d_nsum[sDst[tid]], w);
        float s = beaP[0];
        const float* ep = sE + tid * PE;
#pragma unroll 8
        for (int k = 0; k < ED; k++) s += ep[k] * sWea[k];
        float we = expf(s);
        sWeat[tid] = we;
        atomicAdd(&d_gsume[sBat[tid]], we);
    }
#pragma unroll
    for (int i = 0; i < 2; i++) {
        int c = tid + i * 256;
        int row = c >> 4, q = c & 15;
        cp16(sB + row * PB3 + q * 4, We1 + (size_t)row * ED + q * 4);
    }
    CP_COMMIT;
    __syncthreads();

    // weighted v4-REDs + Y = m + gmap in place
    {
        int row = tid >> 1, half = tid & 1;
        float wgt = sMatt[row];
        float wee = sWeat[row];
        int dnode = sDst[row];
        int b = sBat[row];
        const float* gm = d_gmap + (size_t)b * HID + half * 64;
        float* mrow = sX + row * PX + half * 64;
        float* mg = d_maggr + (size_t)dnode * HID + half * 64;
#pragma unroll
        for (int j = 0; j < 16; j++) {
            float4 mv = *(const float4*)(mrow + j * 4);
            red4(mg + j * 4, make_float4(mv.x * wgt, mv.y * wgt, mv.z * wgt, mv.w * wgt));
            float4 gv = *(const float4*)(gm + j * 4);
            *(float4*)(mrow + j * 4) =
                make_float4(mv.x + gv.x, mv.y + gv.y, mv.z + gv.z, mv.w + gv.w);
        }
        const float* ep2 = sE + row * PE + half * 32;
        float* ea = d_eaggr + (size_t)b * ED + half * 32;
#pragma unroll
        for (int j = 0; j < 8; j++) {
            float4 ev = *(const float4*)(ep2 + j * 4);
            red4(ea + j * 4, make_float4(ev.x * wee, ev.y * wee, ev.z * wee, ev.w * wee));
        }
    }

    // ================= GEMM3 =================
    float a3[2][4][4];
#pragma unroll
    for (int mt = 0; mt < 2; mt++)
#pragma unroll
        for (int nt = 0; nt < 4; nt++)
#pragma unroll
            for (int i = 0; i < 4; i++) a3[mt][nt][i] = 0.f;

    for (int t = 0; t < 6; t++) {
        CP_WAIT0;
        __syncthreads();
        if (t < 5) {
            int tn = t + 1;
#pragma unroll
            for (int i = 0; i < 2; i++) {
                int c = tid + i * 256;
                int row = c >> 4, q = c & 15;
                cp16(sB + ((tn & 1) * 32 * PB3) + row * PB3 + q * 4,
                     We1 + (size_t)(tn * 32 + row) * ED + q * 4);
            }
            CP_COMMIT;
        }
        const float* At; int padA, coff;
        if (t < 2) { At = sE; padA = PE; coff = t * 32; }
        else       { At = sX; padA = PX; coff = (t - 2) * 32; }
        gemm_tile<4>(a3, At, padA, coff, sB + (t & 1) * 32 * PB3, PB3, wy * 32, wx * 32, g, kq);
    }

    // epilogue 3
#pragma unroll
    for (int mt = 0; mt < 2; mt++) {
        int r0 = wy * 32 + mt * 16 + g;
#pragma unroll
        for (int nt = 0; nt < 4; nt++) {
            int col = wx * 32 + nt * 8 + kq * 2;
            float b0 = sBe1[col], b1 = sBe1[col + 1];
            *(float2*)&sU[r0 * PU + col] =
                make_float2(fmaxf(a3[mt][nt][0] + b0, 0.f), fmaxf(a3[mt][nt][1] + b1, 0.f));
            *(float2*)&sU[(r0 + 8) * PU + col] =
                make_float2(fmaxf(a3[mt][nt][2] + b0, 0.f), fmaxf(a3[mt][nt][3] + b1, 0.f));
        }
    }
#pragma unroll
    for (int i = 0; i < 2; i++) {
        int c = tid + i * 256;
        int row = c >> 4, q = c & 15;
        cp16(sB + row * PB3 + q * 4, We2 + (size_t)row * ED + q * 4);
    }
    CP_COMMIT;

    // ================= GEMM4 =================
#pragma unroll
    for (int mt = 0; mt < 2; mt++)
#pragma unroll
        for (int nt = 0; nt < 4; nt++)
#pragma unroll
            for (int i = 0; i < 4; i++) a3[mt][nt][i] = 0.f;

    for (int t = 0; t < 2; t++) {
        CP_WAIT0;
        __syncthreads();
        if (t < 1) {
#pragma unroll
            for (int i = 0; i < 2; i++) {
                int c = tid + i * 256;
                int row = c >> 4, q = c & 15;
                cp16(sB + (32 * PB3) + row * PB3 + q * 4,
                     We2 + (size_t)(32 + row) * ED + q * 4);
            }
            CP_COMMIT;
        }
        gemm_tile<4>(a3, sU, PU, t * 32, sB + (t & 1) * 32 * PB3, PB3, wy * 32, wx * 32, g, kq);
    }

#pragma unroll
    for (int mt = 0; mt < 2; mt++) {
        int r0 = wy * 32 + mt * 16 + g, r1 = r0 + 8;
#pragma unroll
        for (int nt = 0; nt < 4; nt++) {
            int col = wx * 32 + nt * 8 + kq * 2;
            float b0 = sBe2[col], b1 = sBe2[col + 1];
            float2 e0v = *(const float2*)&sE[r0 * PE + col];
            float2 e1v = *(const float2*)&sE[r1 * PE + col];
            *(float2*)&eout[(size_t)(e0 + r0) * ED + col] =
                make_float2(fmaxf(e0v.x + a3[mt][nt][0] + b0, 0.f),
                            fmaxf(e0v.y + a3[mt][nt][1] + b1, 0.f));
            *(float2*)&eout[(size_t)(e0 + r1) * ED + col] =
                make_float2(fmaxf(e1v.x + a3[mt][nt][2] + b0, 0.f),
                            fmaxf(e1v.y + a3[mt][nt][3] + b1, 0.f));
        }
    }
}

// ---------------- node update: 64-row tiles, 128 threads ----------------
__global__ __launch_bounds__(128, 1) void k_node(
    const float* __restrict__ h, const int* __restrict__ batch,
    const float* __restrict__ Wh1, const float* __restrict__ bh1,
    const float* __restrict__ Wh2, const float* __restrict__ bh2,
    float* __restrict__ hout)
{
    extern __shared__ float smp[];
    float* sZ  = smp;                  // 64*PX
    float* sX1 = sZ + 64 * PX;         // 64*PX
    float* sA  = sX1 + 64 * PX;        // 2*64*PA
    float* sB  = sA + 2 * 64 * PA;     // 2*32*PB
    float* sB1 = sB + 2 * 32 * PB;     // 128
    float* sB2 = sB1 + 128;            // 128
    int*   sN  = (int*)(sB2 + 128);    // 64

    const int tid  = threadIdx.x;
    const int lane = tid & 31;
    const int wid  = tid >> 5;         // 0..3
    const int wy   = wid >> 1;         // 0..1 : rows [wy*32, +32)
    const int wx   = wid & 1;          // 0..1 : cols [wx*64, +64)
    const int g    = lane >> 2;
    const int kq   = lane & 3;
    const int n0   = blockIdx.x * 64;

    if (tid < 64) {
        int n = n0 + tid;
        if (n >= NND) n = NND - 1;
        sN[tid] = n;
    }
    sB1[tid] = bh1[tid];
    sB2[tid] = bh2[tid];
    __syncthreads();

    // stage A tile0 (h k0..31) + B tile0 (Wh1 k0..31)
#pragma unroll
    for (int i = 0; i < 4; i++) {                 // 64 rows x 8 float4
        int c = tid + i * 128;
        int row = c >> 3, q = c & 7;
        cp16(sA + row * PA + q * 4, h + (size_t)sN[row] * HD + q * 4);
    }
#pragma unroll
    for (int i = 0; i < 8; i++) {                 // 32 rows x 32 float4
        int c = tid + i * 128;
        int row = c >> 5, q = c & 31;
        cp16(sB + row * PB + q * 4, Wh1 + (size_t)row * HID + q * 4);
    }
    CP_COMMIT;

    // build sZ = maggr/nsum + gmap  (64 rows x 128 cols)
    {
        int row = tid >> 1, halfc = (tid & 1) * 64;
        int n = sN[row];
        float inv = 1.f / (d_nsum[n] + 1e-16f);
        const float* gm = d_gmap + (size_t)batch[n] * HID + halfc;
        const float* mg = d_maggr + (size_t)n * HID + halfc;
        float* zr = sZ + row * PX + halfc;
#pragma unroll
        for (int j = 0; j < 16; j++) {
            float4 mv = *(const float4*)(mg + j * 4);
            float4 gv = *(const float4*)(gm + j * 4);
            *(float4*)(zr + j * 4) =
                make_float4(mv.x * inv + gv.x, mv.y * inv + gv.y,
                            mv.z * inv + gv.z, mv.w * inv + gv.w);
        }
    }

    // ============ GEMM1: [h | z](256) @ Wh1 -> X1 ============
    float acc[2][8][4];
#pragma unroll
    for (int mt = 0; mt < 2; mt++)
#pragma unroll
        for (int nt = 0; nt < 8; nt++)
#pragma unroll
            for (int i = 0; i < 4; i++) acc[mt][nt][i] = 0.f;

    for (int t = 0; t < 8; t++) {
        CP_WAIT0;
        __syncthreads();
        if (t < 7) {
            int tn = t + 1;
            if (tn < 4) {
#pragma unroll
                for (int i = 0; i < 4; i++) {
                    int c = tid + i * 128;
                    int row = c >> 3, q = c & 7;
                    cp16(sA + ((tn & 1) * 64 * PA) + row * PA + q * 4,
                         h + (size_t)sN[row] * HD + tn * 32 + q * 4);
                }
            }
#pragma unroll
            for (int i = 0; i < 8; i++) {
                int c = tid + i * 128;
                int row = c >> 5, q = c & 31;
                cp16(sB + ((tn & 1) * 32 * PB) + row * PB + q * 4,
                     Wh1 + (size_t)(tn * 32 + row) * HID + q * 4);
            }
            CP_COMMIT;
        }
        const float* At; int padA, coff;
        if (t < 4) { At = sA + (t & 1) * 64 * PA; padA = PA; coff = 0; }
        else       { At = sZ; padA = PX; coff = (t - 4) * 32; }
        gemm_tile<8>(acc, At, padA, coff, sB + (t & 1) * 32 * PB, PB, wy * 32, wx * 64, g, kq);
    }

    // epilogue 1: X1 = relu(acc + bh1)
#pragma unroll
    for (int mt = 0; mt < 2; mt++) {
        int r0 = wy * 32 + mt * 16 + g;
#pragma unroll
        for (int nt = 0; nt < 8; nt++) {
            int col = wx * 64 + nt * 8 + kq * 2;
            float b0 = sB1[col], b1 = sB1[col + 1];
            *(float2*)&sX1[r0 * PX + col] =
                make_float2(fmaxf(acc[mt][nt][0] + b0, 0.f), fmaxf(acc[mt][nt][1] + b1, 0.f));
            *(float2*)&sX1[(r0 + 8) * PX + col] =
                make_float2(fmaxf(acc[mt][nt][2] + b0, 0.f), fmaxf(acc[mt][nt][3] + b1, 0.f));
        }
    }
    __syncthreads();

    // stage Wh2 tile0
#pragma unroll
    for (int i = 0; i < 8; i++) {
        int c = tid + i * 128;
        int row = c >> 5, q = c & 31;
        cp16(sB + row * PB + q * 4, Wh2 + (size_t)row * HID + q * 4);
    }
    CP_COMMIT;

    // ============ GEMM2: X1 @ Wh2 ============
#pragma unroll
    for (int mt = 0; mt < 2; mt++)
#pragma unroll
        for (int nt = 0; nt < 8; nt++)
#pragma unroll
            for (int i = 0; i < 4; i++) acc[mt][nt][i] = 0.f;

    for (int t = 0; t < 4; t++) {
        CP_WAIT0;
        __syncthreads();
        if (t < 3) {
            int tn = t + 1;
#pragma unroll
            for (int i = 0; i < 8; i++) {
                int c = tid + i * 128;
                int row = c >> 5, q = c & 31;
                cp16(sB + ((tn & 1) * 32 * PB) + row * PB + q * 4,
                     Wh2 + (size_t)(tn * 32 + row) * HID + q * 4);
            }
            CP_COMMIT;
        }
        gemm_tile<8>(acc, sX1, PX, t * 32, sB + (t & 1) * 32 * PB, PB, wy * 32, wx * 64, g, kq);
    }

    // epilogue 2: hout = relu(h + acc + bh2)
#pragma unroll
    for (int mt = 0; mt < 2; mt++) {
        int r0 = wy * 32 + mt * 16 + g, r1 = r0 + 8;
        int nn0 = n0 + r0, nn1 = n0 + r1;
#pragma unroll
        for (int nt = 0; nt < 8; nt++) {
            int col = wx * 64 + nt * 8 + kq * 2;
            float b0 = sB2[col], b1 = sB2[col + 1];
            if (nn0 < NND) {
                float2 hv = *(const float2*)(h + (size_t)nn0 * HD + col);
                *(float2*)&hout[(size_t)nn0 * HD + col] =
                    make_float2(fmaxf(hv.x + acc[mt][nt][0] + b0, 0.f),
                                fmaxf(hv.y + acc[mt][nt][1] + b1, 0.f));
            }
            if (nn1 < NND) {
                float2 hv = *(const float2*)(h + (size_t)nn1 * HD + col);
                *(float2*)&hout[(size_t)nn1 * HD + col] =
                    make_float2(fmaxf(hv.x + acc[mt][nt][2] + b0, 0.f),
                                fmaxf(hv.y + acc[mt][nt][3] + b1, 0.f));
            }
        }
    }
}

// ---------------- graph update ----------------
__global__ void k_graph(const float* __restrict__ g,
                        const float* __restrict__ Wg1, const float* __restrict__ bg1,
                        const float* __restrict__ Wg2, const float* __restrict__ bg2,
                        float* __restrict__ gout) {
    int r = blockIdx.x, c = threadIdx.x;
    __shared__ float sin_[256];
    __shared__ float t_[64];
    float invh = 1.f / (d_gsumh[r] + 1e-16f);
    float inve = 1.f / (d_gsume[r] + 1e-16f);
    sin_[c] = g[r * GD + c];
    for (int i = c; i < HD; i += 64) sin_[GD + i] = d_haggr[r * HD + i] * invh;
    sin_[GD + HD + c] = d_eaggr[r * ED + c] * inve;
    __syncthreads();
    float s = bg1[c];
#pragma unroll 8
    for (int k = 0; k < 256; k++) s += sin_[k] * Wg1[k * GD + c];
    t_[c] = fmaxf(s, 0.f);
    __syncthreads();
    float u = bg2[c];
#pragma unroll
    for (int k = 0; k < 64; k++) u += t_[k] * Wg2[k * GD + c];
    gout[r * GD + c] = fmaxf(g[r * GD + c] + u, 0.f);
}

// ---------------- launcher ----------------
extern "C" void kernel_launch(void* const* d_in, const int* in_sizes, int n_in,
                              void* d_out, int out_size)
{
    const float* h    = (const float*)d_in[0];
    const float* e    = (const float*)d_in[1];
    const float* g    = (const float*)d_in[2];
    const int*   eidx = (const int*)d_in[3];
    const int*   batch= (const int*)d_in[4];
    const float* Wmap = (const float*)d_in[5];  const float* bmap = (const float*)d_in[6];
    const float* Wm1  = (const float*)d_in[7];  const float* bm1  = (const float*)d_in[8];
    const float* Wm2  = (const float*)d_in[9];  const float* bm2  = (const float*)d_in[10];
    const float* Wma  = (const float*)d_in[11]; const float* bma  = (const float*)d_in[12];
    const float* Wh1  = (const float*)d_in[13]; const float* bh1  = (const float*)d_in[14];
    const float* Wh2  = (const float*)d_in[15]; const float* bh2  = (const float*)d_in[16];
    const float* Wha  = (const float*)d_in[17]; const float* bha  = (const float*)d_in[18];
    const float* We1  = (const float*)d_in[19]; const float* be1  = (const float*)d_in[20];
    const float* We2  = (const float*)d_in[21]; const float* be2  = (const float*)d_in[22];
    const float* Wea  = (const float*)d_in[23]; const float* bea  = (const float*)d_in[24];
    const float* Wg1  = (const float*)d_in[25]; const float* bg1  = (const float*)d_in[26];
    const float* Wg2  = (const float*)d_in[27]; const float* bg2  = (const float*)d_in[28];

    float* out   = (float*)d_out;
    float* out_h = out;
    float* out_e = out + (size_t)NND * HD;
    float* out_g = out + (size_t)NND * HD + (size_t)NE * ED;

    const int SMEM_EDGE =
        (128 * PE + 128 * PX + 3 * 128 * PA + 3 * 32 * PB +
         128 + 64 + 128 + 128 + 128 + 128 + 64 + 64 + 3 * 128) * 4;
    const int SMEM_NODE =
        (2 * 64 * PX + 2 * 64 * PA + 2 * 32 * PB + 128 + 128) * 4 + 64 * 4;

    cudaFuncSetAttribute(k_edge, cudaFuncAttributeMaxDynamicSharedMemorySize, SMEM_EDGE);
    cudaFuncSetAttribute(k_node, cudaFuncAttributeMaxDynamicSharedMemorySize, SMEM_NODE);

    k_initg<<<NG * HID / 256, 256>>>(g, Wmap, bmap);
    k_hagg<<<(NND * 32 + 255) / 256, 256>>>(h, batch, Wha, bha);
    k_edge<<<NE / 128, 256, SMEM_EDGE>>>(h, e, eidx, batch,
                                         Wm1, bm1, Wm2, bm2, Wma, bma,
                                         We1, be1, We2, be2, Wea, bea, out_e);
    k_node<<<(NND + 63) / 64, 128, SMEM_NODE>>>(h, batch, Wh1, bh1, Wh2, bh2, out_h);
    k_graph<<<NG, 64>>>(g, Wg1, bg1, Wg2, bg2, out_g);
}

// round 17
// speedup vs baseline: 1.0113x; 1.0113x over previous
#include <cuda_runtime.h>

#define NND 20000
#define NE  640000
#define NG  256
#define HD  128
#define ED  64
#define GD  64
#define HID 128

#define PE  68
#define PX  132
#define PU  68
#define PA  36
#define PB  136
#define PB3 72

// ---------------- scratch ----------------
__device__ float d_gmap[NG * HID];
__device__ float d_nsum[NND];
__device__ float d_maggr[(size_t)NND * HID];
__device__ float d_gsumh[NG];
__device__ float d_gsume[NG];
__device__ float d_haggr[NG * HID];
__device__ float d_eaggr[NG * ED];

// ---------------- helpers ----------------
__device__ __forceinline__ void mma8(float* c, const unsigned* a, const unsigned* b) {
    asm volatile(
        "mma.sync.aligned.m16n8k8.row.col.f32.tf32.tf32.f32 "
        "{%0,%1,%2,%3}, {%4,%5,%6,%7}, {%8,%9}, {%0,%1,%2,%3};"
        : "+f"(c[0]), "+f"(c[1]), "+f"(c[2]), "+f"(c[3])
        : "r"(a[0]), "r"(a[1]), "r"(a[2]), "r"(a[3]), "r"(b[0]), "r"(b[1]));
}
__device__ __forceinline__ void cp16(void* s, const void* g) {
    unsigned sa = (unsigned)__cvta_generic_to_shared(s);
    asm volatile("cp.async.cg.shared.global [%0], [%1], 16;" :: "r"(sa), "l"(g));
}
#define CP_COMMIT asm volatile("cp.async.commit_group;")
#define CP_WAIT0  asm volatile("cp.async.wait_group 0;")
#define CP_WAIT1  asm volatile("cp.async.wait_group 1;")

__device__ __forceinline__ void red4(float* g, float4 v) {
    asm volatile("red.global.add.v4.f32 [%0], {%1,%2,%3,%4};"
                 :: "l"(g), "f"(v.x), "f"(v.y), "f"(v.z), "f"(v.w) : "memory");
}
__device__ __forceinline__ void ldsmA(unsigned* a, const float* p) {
    unsigned addr = (unsigned)__cvta_generic_to_shared(p);
    asm volatile("ldmatrix.sync.aligned.m8n8.x4.shared.b16 {%0,%1,%2,%3}, [%4];"
                 : "=r"(a[0]), "=r"(a[1]), "=r"(a[2]), "=r"(a[3]) : "r"(addr));
}

// warp-tile GEMM step over one 32-wide k-tile. mt=2 fixed, NT n-tiles of 8 cols.
template <int NT>
__device__ __forceinline__ void gemm_tile(float (*c)[NT][4],
                                          const float* __restrict__ At, int padA, int coff,
                                          const float* __restrict__ Bt, int padB,
                                          int rbase, int cbase, int g, int kq) {
    const int lane = (g << 2) | kq;
    const int rsel = lane & 15;
    const int csel = (lane >> 4) << 2;
#pragma unroll
    for (int k8 = 0; k8 < 4; k8++) {
        unsigned a[2][4];
#pragma unroll
        for (int mt = 0; mt < 2; mt++) {
            const float* p = At + (rbase + mt * 16 + rsel) * padA + coff + k8 * 8 + csel;
            ldsmA(a[mt], p);
        }
        unsigned b[NT][2];
#pragma unroll
        for (int nt = 0; nt < NT; nt++) {
            const float* p = Bt + (k8 * 8 + kq) * padB + cbase + nt * 8 + g;
            b[nt][0] = __float_as_uint(p[0]);
            b[nt][1] = __float_as_uint(p[4 * padB]);
        }
#pragma unroll
        for (int mt = 0; mt < 2; mt++)
#pragma unroll
            for (int nt = 0; nt < NT; nt++) mma8(c[mt][nt], a[mt], b[nt]);
    }
}

// ---------------- merged init + g_map (32768 threads) ----------------
__global__ void k_initg(const float* __restrict__ g, const float* __restrict__ Wmap,
                        const float* __restrict__ bmap) {
    int i = blockIdx.x * blockDim.x + threadIdx.x;   // 0..32767
    int r = i >> 7, c = i & 127;
    float s = bmap[c];
#pragma unroll 8
    for (int k = 0; k < GD; k++) s += __ldg(g + r * GD + k) * __ldg(Wmap + k * HID + c);
    d_gmap[i] = s;
    d_haggr[i] = 0.f;
    if (i < NG) { d_gsumh[i] = 0.f; d_gsume[i] = 0.f; }
    if (i < NG * ED) d_eaggr[i] = 0.f;
}

// ---------------- node->graph aggregation + zero-fill ----------------
__global__ void k_hagg(const float* __restrict__ h, const int* __restrict__ batch,
                       const float* __restrict__ Wha, const float* __restrict__ bhaP) {
    int w = (blockIdx.x * blockDim.x + threadIdx.x) >> 5;
    int lane = threadIdx.x & 31;
    if (w >= NND) return;
    *(float4*)(d_maggr + (size_t)w * HID + lane * 4) = make_float4(0.f, 0.f, 0.f, 0.f);
    if (lane == 0) d_nsum[w] = 0.f;
    float4 hv = *(const float4*)(h + (size_t)w * HD + lane * 4);
    float4 wv = *(const float4*)(Wha + lane * 4);
    float s = hv.x * wv.x + hv.y * wv.y + hv.z * wv.z + hv.w * wv.w;
#pragma unroll
    for (int off = 16; off; off >>= 1) s += __shfl_xor_sync(0xffffffffu, s, off);
    int b = batch[w];
    float ew = expf(s + bhaP[0]);
    if (lane == 0) atomicAdd(&d_gsumh[b], ew);
    red4(d_haggr + b * HD + lane * 4,
         make_float4(hv.x * ew, hv.y * ew, hv.z * ew, hv.w * ew));
}

// ---------------- fused edge kernel (exact R8 configuration) ----------------
__global__ __launch_bounds__(256, 1) void k_edge(
    const float* __restrict__ h, const float* __restrict__ e,
    const int* __restrict__ eidx, const int* __restrict__ batch,
    const float* __restrict__ Wm1, const float* __restrict__ bm1,
    const float* __restrict__ Wm2, const float* __restrict__ bm2,
    const float* __restrict__ Wma, const float* __restrict__ bmaP,
    const float* __restrict__ We1, const float* __restrict__ be1,
    const float* __restrict__ We2, const float* __restrict__ be2,
    const float* __restrict__ Wea, const float* __restrict__ beaP,
    float* __restrict__ eout)
{
    extern __shared__ float smp[];
    float* sE    = smp;                       // 128*PE
    float* sX    = sE + 128 * PE;             // 128*PX
    float* sA    = sX + 128 * PX;             // 3*128*PA
    float* sU    = sA;                        // alias: sA dead after GEMM1
    float* sB    = sA + 3 * 128 * PA;         // 3*32*PB
    float* sWma  = sB + 3 * 32 * PB;
    float* sWea  = sWma + 128;
    float* sMatt = sWea + 64;
    float* sWeat = sMatt + 128;
    float* sBm1  = sWeat + 128;
    float* sBm2  = sBm1 + 128;
    float* sBe1  = sBm2 + 128;
    float* sBe2  = sBe1 + 64;
    int* sDst = (int*)(sBe2 + 64);
    int* sSrc = sDst + 128;
    int* sBat = sSrc + 128;

    const int tid  = threadIdx.x;
    const int lane = tid & 31;
    const int wid  = tid >> 5;
    const int wy   = wid >> 1;
    const int wx   = wid & 1;
    const int g    = lane >> 2;
    const int kq   = lane & 3;
    const int e0   = blockIdx.x * 128;

    if (tid < 128) {
        int d = eidx[NE + e0 + tid];
        sDst[tid] = d;
        sSrc[tid] = eidx[e0 + tid];
        sBat[tid] = batch[d];
        sWma[tid] = Wma[tid];
        sMatt[tid] = bmaP[0];
        sBm1[tid] = bm1[tid];
        sBm2[tid] = bm2[tid];
    }
    if (tid < 64) { sWea[tid] = Wea[tid]; sBe1[tid] = be1[tid]; sBe2[tid] = be2[tid]; }
    __syncthreads();

#pragma unroll
    for (int i = 0; i < 8; i++) {
        int c = tid + i * 256;
        int row = c >> 4, q = c & 15;
        cp16(sE + row * PE + q * 4, e + (size_t)(e0 + row) * ED + q * 4);
    }
#pragma unroll
    for (int i = 0; i < 4; i++) {
        int c = tid + i * 256;
        int row = c >> 3, q = c & 7;
        cp16(sA + row * PA + q * 4, h + (size_t)sDst[row] * HD + q * 4);
    }
#pragma unroll
    for (int i = 0; i < 4; i++) {
        int c = tid + i * 256;
        int row = c >> 5, q = c & 31;
        cp16(sB + row * PB + q * 4, Wm1 + (size_t)row * HID + q * 4);
    }
    CP_COMMIT;
#pragma unroll
    for (int i = 0; i < 4; i++) {
        int c = tid + i * 256;
        int row = c >> 3, q = c & 7;
        cp16(sA + 128 * PA + row * PA + q * 4, h + (size_t)sDst[row] * HD + 32 + q * 4);
    }
#pragma unroll
    for (int i = 0; i < 4; i++) {
        int c = tid + i * 256;
        int row = c >> 5, q = c & 31;
        cp16(sB + 32 * PB + row * PB + q * 4, Wm1 + (size_t)(32 + row) * HID + q * 4);
    }
    CP_COMMIT;

    // ================= GEMM1: [128,320] @ Wm1 -> X (3-stage) =================
    float acc[2][8][4];
#pragma unroll
    for (int mt = 0; mt < 2; mt++)
#pragma unroll
        for (int nt = 0; nt < 8; nt++)
#pragma unroll
            for (int i = 0; i < 4; i++) acc[mt][nt][i] = 0.f;

    for (int t = 0; t < 10; t++) {
        if (t < 9) { CP_WAIT1; } else { CP_WAIT0; }
        __syncthreads();
        int tn = t + 2;
        if (tn <= 9) {
            int buf = tn - (tn / 3) * 3;
            if (tn < 8) {
#pragma unroll
                for (int i = 0; i < 4; i++) {
                    int c = tid + i * 256;
                    int row = c >> 3, q = c & 7;
                    const float* src = (tn < 4)
                        ? h + (size_t)sDst[row] * HD + tn * 32 + q * 4
                        : h + (size_t)sSrc[row] * HD + (tn - 4) * 32 + q * 4;
                    cp16(sA + buf * 128 * PA + row * PA + q * 4, src);
                }
            }
#pragma unroll
            for (int i = 0; i < 4; i++) {
                int c = tid + i * 256;
                int row = c >> 5, q = c & 31;
                cp16(sB + buf * 32 * PB + row * PB + q * 4,
                     Wm1 + (size_t)(tn * 32 + row) * HID + q * 4);
            }
            CP_COMMIT;
        }
        int cbuf = t - (t / 3) * 3;
        const float* At; int padA, coff;
        if (t < 8) { At = sA + cbuf * 128 * PA; padA = PA; coff = 0; }
        else       { At = sE; padA = PE; coff = (t - 8) * 32; }
        gemm_tile<8>(acc, At, padA, coff, sB + cbuf * 32 * PB, PB, wy * 32, wx * 64, g, kq);
    }

    // epilogue 1
#pragma unroll
    for (int mt = 0; mt < 2; mt++) {
        int r0 = wy * 32 + mt * 16 + g;
#pragma unroll
        for (int nt = 0; nt < 8; nt++) {
            int col = wx * 64 + nt * 8 + kq * 2;
            float b0 = sBm1[col], b1 = sBm1[col + 1];
            *(float2*)&sX[r0 * PX + col] =
                make_float2(fmaxf(acc[mt][nt][0] + b0, 0.f), fmaxf(acc[mt][nt][1] + b1, 0.f));
            *(float2*)&sX[(r0 + 8) * PX + col] =
                make_float2(fmaxf(acc[mt][nt][2] + b0, 0.f), fmaxf(acc[mt][nt][3] + b1, 0.f));
        }
    }
    __syncthreads();

#pragma unroll
    for (int i = 0; i < 4; i++) {
        int c = tid + i * 256;
        int row = c >> 5, q = c & 31;
        cp16(sB + row * PB + q * 4, Wm2 + (size_t)row * HID + q * 4);
    }
    CP_COMMIT;

    // ================= GEMM2 =================
#pragma unroll
    for (int mt = 0; mt < 2; mt++)
#pragma unroll
        for (int nt = 0; nt < 8; nt++)
#pragma unroll
            for (int i = 0; i < 4; i++) acc[mt][nt][i] = 0.f;

    for (int t = 0; t < 4; t++) {
        CP_WAIT0;
        __syncthreads();
        if (t < 3) {
            int tn = t + 1;
#pragma unroll
            for (int i = 0; i < 4; i++) {
                int c = tid + i * 256;
                int row = c >> 5, q = c & 31;
                cp16(sB + ((tn & 1) * 32 * PB) + row * PB + q * 4,
                     Wm2 + (size_t)(tn * 32 + row) * HID + q * 4);
            }
            CP_COMMIT;
        }
        gemm_tile<8>(acc, sX, PX, t * 32, sB + (t & 1) * 32 * PB, PB, wy * 32, wx * 64, g, kq);
    }
    __syncthreads();

    // epilogue 2
    {
        float pa[4] = {0.f, 0.f, 0.f, 0.f};
#pragma unroll
        for (int mt = 0; mt < 2; mt++) {
            int r0 = wy * 32 + mt * 16 + g;
#pragma unroll
            for (int nt = 0; nt < 8; nt++) {
                int col = wx * 64 + nt * 8 + kq * 2;
                float b0 = sBm2[col], b1 = sBm2[col + 1];
                float v0 = fmaxf(acc[mt][nt][0] + b0, 0.f);
                float v1 = fmaxf(acc[mt][nt][1] + b1, 0.f);
                float v2 = fmaxf(acc[mt][nt][2] + b0, 0.f);
                float v3 = fmaxf(acc[mt][nt][3] + b1, 0.f);
                *(float2*)&sX[r0 * PX + col]       = make_float2(v0, v1);
                *(float2*)&sX[(r0 + 8) * PX + col] = make_float2(v2, v3);
                float w0 = sWma[col], w1 = sWma[col + 1];
                pa[mt * 2 + 0] += v0 * w0 + v1 * w1;
                pa[mt * 2 + 1] += v2 * w0 + v3 * w1;
            }
        }
#pragma unroll
        for (int off = 1; off <= 2; off <<= 1)
#pragma unroll
            for (int i = 0; i < 4; i++) pa[i] += __shfl_xor_sync(0xffffffffu, pa[i], off);
        if (kq == 0) {
            atomicAdd(&sMatt[wy * 32 + g],      pa[0]);
            atomicAdd(&sMatt[wy * 32 + g + 8],  pa[1]);
            atomicAdd(&sMatt[wy * 32 + g + 16], pa[2]);
            atomicAdd(&sMatt[wy * 32 + g + 24], pa[3]);
        }
    }
    __syncthreads();

    if (tid < 128) {
        float w = expf(sMatt[tid]);
        sMatt[tid] = w;
        atomicAdd(&d_nsum[sDst[tid]], w);
        float s = beaP[0];
        const float* ep = sE + tid * PE;
#pragma unroll 8
        for (int k = 0; k < ED; k++) s += ep[k] * sWea[k];
        float we = expf(s);
        sWeat[tid] = we;
        atomicAdd(&d_gsume[sBat[tid]], we);
    }
#pragma unroll
    for (int i = 0; i < 2; i++) {
        int c = tid + i * 256;
        int row = c >> 4, q = c & 15;
        cp16(sB + row * PB3 + q * 4, We1 + (size_t)row * ED + q * 4);
    }
    CP_COMMIT;
    __syncthreads();

    // weighted v4-REDs + Y = m + gmap in place
    {
        int row = tid >> 1, half = tid & 1;
        float wgt = sMatt[row];
        float wee = sWeat[row];
        int dnode = sDst[row];
        int b = sBat[row];
        const float* gm = d_gmap + (size_t)b * HID + half * 64;
        float* mrow = sX + row * PX + half * 64;
        float* mg = d_maggr + (size_t)dnode * HID + half * 64;
#pragma unroll
        for (int j = 0; j < 16; j++) {
            float4 mv = *(const float4*)(mrow + j * 4);
            red4(mg + j * 4, make_float4(mv.x * wgt, mv.y * wgt, mv.z * wgt, mv.w * wgt));
            float4 gv = *(const float4*)(gm + j * 4);
            *(float4*)(mrow + j * 4) =
                make_float4(mv.x + gv.x, mv.y + gv.y, mv.z + gv.z, mv.w + gv.w);
        }
        const float* ep2 = sE + row * PE + half * 32;
        float* ea = d_eaggr + (size_t)b * ED + half * 32;
#pragma unroll
        for (int j = 0; j < 8; j++) {
            float4 ev = *(const float4*)(ep2 + j * 4);
            red4(ea + j * 4, make_float4(ev.x * wee, ev.y * wee, ev.z * wee, ev.w * wee));
        }
    }

    // ================= GEMM3 =================
    float a3[2][4][4];
#pragma unroll
    for (int mt = 0; mt < 2; mt++)
#pragma unroll
        for (int nt = 0; nt < 4; nt++)
#pragma unroll
            for (int i = 0; i < 4; i++) a3[mt][nt][i] = 0.f;

    for (int t = 0; t < 6; t++) {
        CP_WAIT0;
        __syncthreads();
        if (t < 5) {
            int tn = t + 1;
#pragma unroll
            for (int i = 0; i < 2; i++) {
                int c = tid + i * 256;
                int row = c >> 4, q = c & 15;
                cp16(sB + ((tn & 1) * 32 * PB3) + row * PB3 + q * 4,
                     We1 + (size_t)(tn * 32 + row) * ED + q * 4);
            }
            CP_COMMIT;
        }
        const float* At; int padA, coff;
        if (t < 2) { At = sE; padA = PE; coff = t * 32; }
        else       { At = sX; padA = PX; coff = (t - 2) * 32; }
        gemm_tile<4>(a3, At, padA, coff, sB + (t & 1) * 32 * PB3, PB3, wy * 32, wx * 32, g, kq);
    }

    // epilogue 3
#pragma unroll
    for (int mt = 0; mt < 2; mt++) {
        int r0 = wy * 32 + mt * 16 + g;
#pragma unroll
        for (int nt = 0; nt < 4; nt++) {
            int col = wx * 32 + nt * 8 + kq * 2;
            float b0 = sBe1[col], b1 = sBe1[col + 1];
            *(float2*)&sU[r0 * PU + col] =
                make_float2(fmaxf(a3[mt][nt][0] + b0, 0.f), fmaxf(a3[mt][nt][1] + b1, 0.f));
            *(float2*)&sU[(r0 + 8) * PU + col] =
                make_float2(fmaxf(a3[mt][nt][2] + b0, 0.f), fmaxf(a3[mt][nt][3] + b1, 0.f));
        }
    }
#pragma unroll
    for (int i = 0; i < 2; i++) {
        int c = tid + i * 256;
        int row = c >> 4, q = c & 15;
        cp16(sB + row * PB3 + q * 4, We2 + (size_t)row * ED + q * 4);
    }
    CP_COMMIT;

    // ================= GEMM4 =================
#pragma unroll
    for (int mt = 0; mt < 2; mt++)
#pragma unroll
        for (int nt = 0; nt < 4; nt++)
#pragma unroll
            for (int i = 0; i < 4; i++) a3[mt][nt][i] = 0.f;

    for (int t = 0; t < 2; t++) {
        CP_WAIT0;
        __syncthreads();
        if (t < 1) {
#pragma unroll
            for (int i = 0; i < 2; i++) {
                int c = tid + i * 256;
                int row = c >> 4, q = c & 15;
                cp16(sB + (32 * PB3) + row * PB3 + q * 4,
                     We2 + (size_t)(32 + row) * ED + q * 4);
            }
            CP_COMMIT;
        }
        gemm_tile<4>(a3, sU, PU, t * 32, sB + (t & 1) * 32 * PB3, PB3, wy * 32, wx * 32, g, kq);
    }

#pragma unroll
    for (int mt = 0; mt < 2; mt++) {
        int r0 = wy * 32 + mt * 16 + g, r1 = r0 + 8;
#pragma unroll
        for (int nt = 0; nt < 4; nt++) {
            int col = wx * 32 + nt * 8 + kq * 2;
            float b0 = sBe2[col], b1 = sBe2[col + 1];
            float2 e0v = *(const float2*)&sE[r0 * PE + col];
            float2 e1v = *(const float2*)&sE[r1 * PE + col];
            *(float2*)&eout[(size_t)(e0 + r0) * ED + col] =
                make_float2(fmaxf(e0v.x + a3[mt][nt][0] + b0, 0.f),
                            fmaxf(e0v.y + a3[mt][nt][1] + b1, 0.f));
            *(float2*)&eout[(size_t)(e0 + r1) * ED + col] =
                make_float2(fmaxf(e1v.x + a3[mt][nt][2] + b0, 0.f),
                            fmaxf(e1v.y + a3[mt][nt][3] + b1, 0.f));
        }
    }
}

// ---------------- node update: tf32 GEMM (exact R8 configuration) -------------
__global__ __launch_bounds__(256, 1) void k_node(
    const float* __restrict__ h, const int* __restrict__ batch,
    const float* __restrict__ Wh1, const float* __restrict__ bh1,
    const float* __restrict__ Wh2, const float* __restrict__ bh2,
    float* __restrict__ hout)
{
    extern __shared__ float smp[];
    float* sZ  = smp;
    float* sX1 = sZ + 128 * PX;
    float* sA  = sX1 + 128 * PX;
    float* sB  = sA + 2 * 128 * PA;
    float* sB1 = sB + 2 * 32 * PB;
    float* sB2 = sB1 + 128;
    int*   sN  = (int*)(sB2 + 128);

    const int tid  = threadIdx.x;
    const int lane = tid & 31;
    const int wid  = tid >> 5;
    const int wy   = wid >> 1;
    const int wx   = wid & 1;
    const int g    = lane >> 2;
    const int kq   = lane & 3;
    const int n0   = blockIdx.x * 128;

    if (tid < 128) {
        int n = n0 + tid;
        if (n >= NND) n = NND - 1;
        sN[tid] = n;
        sB1[tid] = bh1[tid];
        sB2[tid] = bh2[tid];
    }
    __syncthreads();

#pragma unroll
    for (int i = 0; i < 4; i++) {
        int c = tid + i * 256;
        int row = c >> 3, q = c & 7;
        cp16(sA + row * PA + q * 4, h + (size_t)sN[row] * HD + q * 4);
    }
#pragma unroll
    for (int i = 0; i < 4; i++) {
        int c = tid + i * 256;
        int row = c >> 5, q = c & 31;
        cp16(sB + row * PB + q * 4, Wh1 + (size_t)row * HID + q * 4);
    }
    CP_COMMIT;

    {
        int row = tid >> 1, halfc = (tid & 1) * 64;
        int n = sN[row];
        float inv = 1.f / (d_nsum[n] + 1e-16f);
        const float* gm = d_gmap + (size_t)batch[n] * HID + halfc;
        const float* mg = d_maggr + (size_t)n * HID + halfc;
        float* zr = sZ + row * PX + halfc;
#pragma unroll
        for (int j = 0; j < 16; j++) {
            float4 mv = *(const float4*)(mg + j * 4);
            float4 gv = *(const float4*)(gm + j * 4);
            *(float4*)(zr + j * 4) =
                make_float4(mv.x * inv + gv.x, mv.y * inv + gv.y,
                            mv.z * inv + gv.z, mv.w * inv + gv.w);
        }
    }

    float acc[2][8][4];
#pragma unroll
    for (int mt = 0; mt < 2; mt++)
#pragma unroll
        for (int nt = 0; nt < 8; nt++)
#pragma unroll
            for (int i = 0; i < 4; i++) acc[mt][nt][i] = 0.f;

    for (int t = 0; t < 8; t++) {
        CP_WAIT0;
        __syncthreads();
        if (t < 7) {
            int tn = t + 1;
            if (tn < 4) {
#pragma unroll
                for (int i = 0; i < 4; i++) {
                    int c = tid + i * 256;
                    int row = c >> 3, q = c & 7;
                    cp16(sA + ((tn & 1) * 128 * PA) + row * PA + q * 4,
                         h + (size_t)sN[row] * HD + tn * 32 + q * 4);
                }
            }
#pragma unroll
            for (int i = 0; i < 4; i++) {
                int c = tid + i * 256;
                int row = c >> 5, q = c & 31;
                cp16(sB + ((tn & 1) * 32 * PB) + row * PB + q * 4,
                     Wh1 + (size_t)(tn * 32 + row) * HID + q * 4);
            }
            CP_COMMIT;
        }
        const float* At; int padA, coff;
        if (t < 4) { At = sA + (t & 1) * 128 * PA; padA = PA; coff = 0; }
        else       { At = sZ; padA = PX; coff = (t - 4) * 32; }
        gemm_tile<8>(acc, At, padA, coff, sB + (t & 1) * 32 * PB, PB, wy * 32, wx * 64, g, kq);
    }

#pragma unroll
    for (int mt = 0; mt < 2; mt++) {
        int r0 = wy * 32 + mt * 16 + g;
#pragma unroll
        for (int nt = 0; nt < 8; nt++) {
            int col = wx * 64 + nt * 8 + kq * 2;
            float b0 = sB1[col], b1 = sB1[col + 1];
            *(float2*)&sX1[r0 * PX + col] =
                make_float2(fmaxf(acc[mt][nt][0] + b0, 0.f), fmaxf(acc[mt][nt][1] + b1, 0.f));
            *(float2*)&sX1[(r0 + 8) * PX + col] =
                make_float2(fmaxf(acc[mt][nt][2] + b0, 0.f), fmaxf(acc[mt][nt][3] + b1, 0.f));
        }
    }
    __syncthreads();

#pragma unroll
    for (int i = 0; i < 4; i++) {
        int c = tid + i * 256;
        int row = c >> 5, q = c & 31;
        cp16(sB + row * PB + q * 4, Wh2 + (size_t)row * HID + q * 4);
    }
    CP_COMMIT;

#pragma unroll
    for (int mt = 0; mt < 2; mt++)
#pragma unroll
        for (int nt = 0; nt < 8; nt++)
#pragma unroll
            for (int i = 0; i < 4; i++) acc[mt][nt][i] = 0.f;

    for (int t = 0; t < 4; t++) {
        CP_WAIT0;
        __syncthreads();
        if (t < 3) {
            int tn = t + 1;
#pragma unroll
            for (int i = 0; i < 4; i++) {
                int c = tid + i * 256;
                int row = c >> 5, q = c & 31;
                cp16(sB + ((tn & 1) * 32 * PB) + row * PB + q * 4,
                     Wh2 + (size_t)(tn * 32 + row) * HID + q * 4);
            }
            CP_COMMIT;
        }
        gemm_tile<8>(acc, sX1, PX, t * 32, sB + (t & 1) * 32 * PB, PB, wy * 32, wx * 64, g, kq);
    }

#pragma unroll
    for (int mt = 0; mt < 2; mt++) {
        int r0 = wy * 32 + mt * 16 + g, r1 = r0 + 8;
        int nn0 = n0 + r0, nn1 = n0 + r1;
#pragma unroll
        for (int nt = 0; nt < 8; nt++) {
            int col = wx * 64 + nt * 8 + kq * 2;
            float b0 = sB2[col], b1 = sB2[col + 1];
            if (nn0 < NND) {
                float2 hv = *(const float2*)(h + (size_t)nn0 * HD + col);
                *(float2*)&hout[(size_t)nn0 * HD + col] =
                    make_float2(fmaxf(hv.x + acc[mt][nt][0] + b0, 0.f),
                                fmaxf(hv.y + acc[mt][nt][1] + b1, 0.f));
            }
            if (nn1 < NND) {
                float2 hv = *(const float2*)(h + (size_t)nn1 * HD + col);
                *(float2*)&hout[(size_t)nn1 * HD + col] =
                    make_float2(fmaxf(hv.x + acc[mt][nt][2] + b0, 0.f),
                                fmaxf(hv.y + acc[mt][nt][3] + b1, 0.f));
            }
        }
    }
}

// ---------------- graph update: 128 threads, split-k layer 1 ----------------
__global__ void k_graph(const float* __restrict__ g,
                        const float* __restrict__ Wg1, const float* __restrict__ bg1,
                        const float* __restrict__ Wg2, const float* __restrict__ bg2,
                        float* __restrict__ gout) {
    int r = blockIdx.x;
    int tid = threadIdx.x;            // 0..127
    int c = tid & 63, half = tid >> 6;
    __shared__ float sin_[256];
    __shared__ float part[128];
    __shared__ float t_[64];
    float invh = 1.f / (d_gsumh[r] + 1e-16f);
    float inve = 1.f / (d_gsume[r] + 1e-16f);
    if (half == 0) sin_[c] = g[r * GD + c];
    for (int i = tid; i < HD; i += 128) sin_[GD + i] = d_haggr[r * HD + i] * invh;
    if (half == 1) sin_[GD + HD + c] = d_eaggr[r * ED + c] * inve;
    __syncthreads();
    float s = (half == 0) ? bg1[c] : 0.f;
    int k0 = half * 128;
#pragma unroll 8
    for (int k = 0; k < 128; k++) s += sin_[k0 + k] * Wg1[(k0 + k) * GD + c];
    part[tid] = s;
    __syncthreads();
    if (half == 0) t_[c] = fmaxf(part[c] + part[c + 64], 0.f);
    __syncthreads();
    if (half == 0) {
        float u = bg2[c];
#pragma unroll
        for (int k = 0; k < 64; k++) u += t_[k] * Wg2[k * GD + c];
        gout[r * GD + c] = fmaxf(g[r * GD + c] + u, 0.f);
    }
}

// ---------------- launcher ----------------
extern "C" void kernel_launch(void* const* d_in, const int* in_sizes, int n_in,
                              void* d_out, int out_size)
{
    const float* h    = (const float*)d_in[0];
    const float* e    = (const float*)d_in[1];
    const float* g    = (const float*)d_in[2];
    const int*   eidx = (const int*)d_in[3];
    const int*   batch= (const int*)d_in[4];
    const float* Wmap = (const float*)d_in[5];  const float* bmap = (const float*)d_in[6];
    const float* Wm1  = (const float*)d_in[7];  const float* bm1  = (const float*)d_in[8];
    const float* Wm2  = (const float*)d_in[9];  const float* bm2  = (const float*)d_in[10];
    const float* Wma  = (const float*)d_in[11]; const float* bma  = (const float*)d_in[12];
    const float* Wh1  = (const float*)d_in[13]; const float* bh1  = (const float*)d_in[14];
    const float* Wh2  = (const float*)d_in[15]; const float* bh2  = (const float*)d_in[16];
    const float* Wha  = (const float*)d_in[17]; const float* bha  = (const float*)d_in[18];
    const float* We1  = (const float*)d_in[19]; const float* be1  = (const float*)d_in[20];
    const float* We2  = (const float*)d_in[21]; const float* be2  = (const float*)d_in[22];
    const float* Wea  = (const float*)d_in[23]; const float* bea  = (const float*)d_in[24];
    const float* Wg1  = (const float*)d_in[25]; const float* bg1  = (const float*)d_in[26];
    const float* Wg2  = (const float*)d_in[27]; const float* bg2  = (const float*)d_in[28];

    float* out   = (float*)d_out;
    float* out_h = out;
    float* out_e = out + (size_t)NND * HD;
    float* out_g = out + (size_t)NND * HD + (size_t)NE * ED;

    const int SMEM_EDGE =
        (128 * PE + 128 * PX + 3 * 128 * PA + 3 * 32 * PB +
         128 + 64 + 128 + 128 + 128 + 128 + 64 + 64 + 3 * 128) * 4;
    const int SMEM_NODE =
        (2 * 128 * PX + 2 * 128 * PA + 2 * 32 * PB + 128 + 128 + 128) * 4;

    cudaFuncSetAttribute(k_edge, cudaFuncAttributeMaxDynamicSharedMemorySize, SMEM_EDGE);
    cudaFuncSetAttribute(k_node, cudaFuncAttributeMaxDynamicSharedMemorySize, SMEM_NODE);

    k_initg<<<NG * HID / 256, 256>>>(g, Wmap, bmap);
    k_hagg<<<(NND * 32 + 255) / 256, 256>>>(h, batch, Wha, bha);
    k_edge<<<NE / 128, 256, SMEM_EDGE>>>(h, e, eidx, batch,
                                         Wm1, bm1, Wm2, bm2, Wma, bma,
                                         We1, be1, We2, be2, Wea, bea, out_e);
    k_node<<<(NND + 127) / 128, 256, SMEM_NODE>>>(h, batch, Wh1, bh1, Wh2, bh2, out_h);
    k_graph<<<NG, 128>>>(g, Wg1, bg1, Wg2, bg2, out_g);
}